// round 2
// baseline (speedup 1.0000x reference)
#include <cuda_runtime.h>

// S4D: y[b,h,l] = sum_{m<=l} k[h,m] * u[b,h,l-m] + D[h]*u[b,h,l]
// with k[h,m] = 2*Re( sum_n Ct[h,n] * w[h,n]^m ), w = exp(dt*A).
// Implemented as the exact diagonal state-space recurrence:
//   x[n,l] = w[n]*x[n,l-1] + u[l];  y[l] = 2*Re(sum_n Ct[n]*x[n,l]) + D*u[l]
//
// One warp per (b,h). Lane = mode n (N2 == 32). Per 32-step tile the per-lane
// projection partials are transposed through shared memory so the cross-mode
// sum costs ~2 ops/step instead of a 5-level shuffle reduction per step.

constexpr int Hh = 256;
constexpr int N2 = 32;
constexpr int Bb = 16;
constexpr int Ll = 8192;
constexpr int WARPS = 8;
constexpr int TILE = 32;

__global__ __launch_bounds__(WARPS * 32, 1)
void s4d_scan_kernel(const float* __restrict__ u,
                     const float* __restrict__ log_dt,
                     const float* __restrict__ log_A_real,
                     const float* __restrict__ A_imag,
                     const float* __restrict__ C,
                     const float* __restrict__ D,
                     float* __restrict__ y)
{
    // 36-float row stride: keeps float4 alignment (36*4 % 16 == 0) and
    // conflict-free banks for both the per-step STS and the row-wise LDS.128.
    __shared__ float sm[WARPS][32][36];

    const int warp = threadIdx.x >> 5;
    const int lane = threadIdx.x & 31;
    const int g = blockIdx.x * WARPS + warp;   // g = b*H + h
    const int h = g & (Hh - 1);

    // ---- per-mode parameters (computed once; use precise libm variants) ----
    const float dt = expf(log_dt[h]);
    const float ar = -expf(log_A_real[h * N2 + lane]);
    const float ai = A_imag[h * N2 + lane];
    const float dtar = ar * dt;
    const float dtai = ai * dt;
    const float mag = expf(dtar);
    const float wr = mag * cosf(dtai);
    const float wi = mag * sinf(dtai);

    // Ct = 2 * C * (w - 1) / A   (complex)
    const float na = ar * ar + ai * ai;
    const float tr = wr - 1.0f, ti = wi;
    const float qr = (tr * ar + ti * ai) / na;
    const float qi = (ti * ar - tr * ai) / na;
    const float cr = C[(h * N2 + lane) * 2 + 0];
    const float ci = C[(h * N2 + lane) * 2 + 1];
    const float Ctr  = 2.0f * (cr * qr - ci * qi);
    const float nCti = -2.0f * (cr * qi + ci * qr);
    const float d = D[h];

    const float* __restrict__ up = u + (size_t)g * Ll;
    float*       __restrict__ yp = y + (size_t)g * Ll;

    float xr = 0.0f, xi = 0.0f;

    for (int base = 0; base < Ll; base += TILE) {
        const float uv = up[base + lane];            // coalesced tile load

        #pragma unroll
        for (int t = 0; t < TILE; ++t) {
            const float ut = __shfl_sync(0xffffffffu, uv, t);
            const float nxr = fmaf(wr, xr, fmaf(-wi, xi, ut));
            const float nxi = fmaf(wi, xr, wr * xi);
            xr = nxr; xi = nxi;
            // projection partial for output l = base + t, mode = lane
            sm[warp][t][lane] = fmaf(Ctr, xr, nCti * xi);
        }
        __syncwarp();

        // lane t sums mode partials for output l = base + t
        const float4* r4 = reinterpret_cast<const float4*>(&sm[warp][lane][0]);
        float s0 = 0.f, s1 = 0.f;
        #pragma unroll
        for (int j = 0; j < 8; j += 2) {
            const float4 v0 = r4[j];
            const float4 v1 = r4[j + 1];
            s0 += (v0.x + v0.y) + (v0.z + v0.w);
            s1 += (v1.x + v1.y) + (v1.z + v1.w);
        }
        yp[base + lane] = fmaf(d, uv, s0 + s1);      // coalesced store
        __syncwarp();
    }
}

extern "C" void kernel_launch(void* const* d_in, const int* in_sizes, int n_in,
                              void* d_out, int out_size)
{
    const float* u          = (const float*)d_in[0];
    const float* log_dt     = (const float*)d_in[1];
    const float* log_A_real = (const float*)d_in[2];
    const float* A_imag     = (const float*)d_in[3];
    const float* C          = (const float*)d_in[4];
    const float* D          = (const float*)d_in[5];
    float* y = (float*)d_out;

    const int seqs = Bb * Hh;                 // 4096 (b,h) sequences
    const int grid = seqs / WARPS;            // 512 blocks of 8 warps
    s4d_scan_kernel<<<grid, WARPS * 32>>>(u, log_dt, log_A_real, A_imag, C, D, y);
}